// round 14
// baseline (speedup 1.0000x reference)
#include <cuda_runtime.h>
#include <cstdint>

// Shapes (fixed):
//   log_probs: (128, 64) f32 | ref: (256, 128) i32 | hyp: (256, 128, 64) i32
#define NBATCH 128
#define NSAMP  64
#define NSEQ   (NBATCH * NSAMP)   // 8192
#define RLEN   256
#define HLEN   256
#define SYMS   1024               // tokens in [0,1000) -> no masking needed
#define TPD    8                  // token prefetch depth == unroll factor

typedef unsigned long long ull;

__device__ double   d_partial[NBATCH];
__device__ unsigned d_ticket;      // zero at start; winner resets each run

// (x << 1) | c  with c in {0,1}, expressed as mad.lo.u64 so ptxas lowers it to
// IMAD (fma pipe) instead of SHF/LEA (alu pipe). Non-volatile: pure value op,
// scheduler keeps full freedom. This offloads the binding alu dispatch port.
__device__ __forceinline__ ull shl1_or(ull x, ull c) {
    ull r;
    asm("mad.lo.u64 %0, %1, 2, %2;" : "=l"(r) : "l"(x), "l"(c));
    return r;
}

// ---------------------------------------------------------------------------
// Branchless Myers bit-parallel DP over NWA 64-bit words, fixed 256 steps,
// unrolled x8. EOS handled by SEL capture (no data-dependent branches).
// TOP=true (pm==63): score bit == word carry-out, reuse po/mo.
// ---------------------------------------------------------------------------
template<int NWA, bool TOP>
__device__ __forceinline__ int myers_run(const ull* __restrict__ sPeq,
                                         const int* __restrict__ hyp,
                                         int n, int pm) {
    ull Pv[NWA], Mv[NWA];
    #pragma unroll
    for (int w = 0; w < NWA; ++w) { Pv[w] = ~0ull; Mv[w] = 0ull; }

    int toks[TPD];
    int tcur = hyp[n];                                    // token for step 0
    #pragma unroll
    for (int k = 0; k < TPD; ++k) toks[k] = hyp[(size_t)(k + 1) * NSEQ + n];

    ull E[NWA];
    #pragma unroll
    for (int w = 0; w < NWA; ++w) E[w] = sPeq[(tcur << 2) + w];

    int score  = 0;     // running delta vs m; caller adds m
    int scoreF = 0;
    int done   = 0;

    #pragma unroll 1
    for (int hb = 0; hb < HLEN; hb += TPD) {
        #pragma unroll
        for (int j = 0; j < TPD; ++j) {
            const int h = hb + j;

            // prefetch next step's Eq from SMEM (LDS.128 pairs)
            const int t1 = toks[j];
            ull N[NWA];
            if (NWA >= 2) {
                ulonglong2 lo = *reinterpret_cast<const ulonglong2*>(&sPeq[t1 << 2]);
                N[0] = lo.x; N[1] = lo.y;
                if (NWA == 3) N[2] = sPeq[(t1 << 2) + 2];
                if (NWA == 4) {
                    ulonglong2 hi = *reinterpret_cast<const ulonglong2*>(&sPeq[(t1 << 2) + 2]);
                    N[2] = hi.x; N[3] = hi.y;
                }
            } else {
                N[0] = sPeq[t1 << 2];
            }

            // refill ring: token for step h+1+TPD (wrapped; value unused when
            // h+1+TPD >= HLEN because those steps never execute)
            const int sa = (h + 1 + TPD) & (HLEN - 1);
            toks[j] = hyp[(size_t)sa * NSEQ + n];

            // Myers word updates (R6-verified algebra; shifts on the fma pipe)
            ull phin = 1ull, mhin = 0ull;   // D[i][0] = i boundary
            #pragma unroll
            for (int w = 0; w < NWA; ++w) {
                ull Eq = E[w];
                ull Xv = Eq | Mv[w];
                Eq |= mhin;
                ull Xh = (((Eq & Pv[w]) + Pv[w]) ^ Pv[w]) | Eq;
                ull Ph = Mv[w] | ~(Xh | Pv[w]);
                ull Mh = Pv[w] & Xh;
                ull po = Ph >> 63, mo = Mh >> 63;
                if (w == NWA - 1) {   // score lives in the top word
                    if (TOP)          // pm==63: score bit IS the carry-out
                        score += (int)po - (int)mo;
                    else
                        score += (int)((Ph >> pm) & 1ull) - (int)((Mh >> pm) & 1ull);
                }
                Ph = shl1_or(Ph, phin);   // IMAD (fma pipe), not SHF (alu pipe)
                Mh = shl1_or(Mh, mhin);
                Pv[w] = Mh | ~(Xv | Ph);
                Mv[w] = Ph & Xv;
                phin = po; mhin = mo;
            }

            // branchless EOS capture: first EOS step (inclusive) latches score
            const int isEos = (tcur == 0);
            scoreF = (isEos & ~done) ? score : scoreF;
            done  |= isEos;

            tcur = t1;
            #pragma unroll
            for (int w = 0; w < NWA; ++w) E[w] = N[w];
        }
    }

    return done ? scoreF : score;
}

// ---------------------------------------------------------------------------
// Fused kernel: block b = batch row b, 64 threads (one per sample).
// ---------------------------------------------------------------------------
__global__ void __launch_bounds__(NSAMP, 1)
mer_loss_kernel(const int* __restrict__ hyp,
                const int* __restrict__ ref,
                const float* __restrict__ logp,
                float* __restrict__ out) {
    __shared__ ull    sPeq[SYMS * 4];   // 32 KB bitmask table
    __shared__ int    sMinEos;
    __shared__ float  sEr[NSAMP];
    __shared__ bool   sLast;
    __shared__ double sSum[NBATCH];

    const int b = blockIdx.x;
    const int s = threadIdx.x;           // 0..63
    const int n = b * NSAMP + s;

    // ---- build Peq in SMEM ----
    if (s == 0) sMinEos = RLEN;
    #pragma unroll
    for (int i = s; i < SYMS * 4; i += NSAMP) sPeq[i] = 0ull;
    __syncthreads();

    int rtok[RLEN / NSAMP];
    #pragma unroll
    for (int k = 0; k < RLEN / NSAMP; ++k) {
        int j = s + k * NSAMP;
        rtok[k] = ref[(size_t)j * NBATCH + b];
        if (rtok[k] == 0) atomicMin(&sMinEos, j);
    }
    __syncthreads();
    const int m = (sMinEos < RLEN) ? (sMinEos + 1) : RLEN;  // INCLUDE_EOS
    #pragma unroll
    for (int k = 0; k < RLEN / NSAMP; ++k) {
        int j = s + k * NSAMP;
        if (j < m)
            atomicOr(&sPeq[(rtok[k] << 2) + (j >> 6)], 1ull << (j & 63));
    }
    __syncthreads();

    const int bsel = (m - 1) >> 6;
    const int pm   = (m - 1) & 63;

    // ---- Myers DP dispatched on uniform (word count, top-bit) ----
    int sdel;
    if (pm == 63) {
        switch (bsel) {
            case 0:  sdel = myers_run<1, true>(sPeq, hyp, n, pm); break;
            case 1:  sdel = myers_run<2, true>(sPeq, hyp, n, pm); break;
            case 2:  sdel = myers_run<3, true>(sPeq, hyp, n, pm); break;
            default: sdel = myers_run<4, true>(sPeq, hyp, n, pm); break;
        }
    } else {
        switch (bsel) {
            case 0:  sdel = myers_run<1, false>(sPeq, hyp, n, pm); break;
            case 1:  sdel = myers_run<2, false>(sPeq, hyp, n, pm); break;
            case 2:  sdel = myers_run<3, false>(sPeq, hyp, n, pm); break;
            default: sdel = myers_run<4, false>(sPeq, hyp, n, pm); break;
        }
    }
    const int score = m + sdel;

    sEr[s] = (float)score / (float)m;
    __syncthreads();

    // ---- per-batch softmax-weighted centered reduction (warp 0) ----
    if (s < 32) {
        int lane = s, base = b * NSAMP;
        float er0 = sEr[lane],         er1 = sEr[lane + 32];
        float lp0 = logp[base + lane], lp1 = logp[base + 32 + lane];

        float mx = fmaxf(lp0, lp1);
        #pragma unroll
        for (int o = 16; o; o >>= 1) mx = fmaxf(mx, __shfl_xor_sync(0xffffffffu, mx, o));

        float e0 = expf(lp0 - mx), e1 = expf(lp1 - mx);
        float se  = e0 + e1;
        float ser = er0 + er1;
        float sep = er0 * e0 + er1 * e1;
        #pragma unroll
        for (int o = 16; o; o >>= 1) {
            se  += __shfl_xor_sync(0xffffffffu, se,  o);
            ser += __shfl_xor_sync(0xffffffffu, ser, o);
            sep += __shfl_xor_sync(0xffffffffu, sep, o);
        }
        if (lane == 0)
            d_partial[b] = (double)sep / (double)se - (double)ser / 64.0;
    }
    __syncthreads();

    // ---- last-block ticket: global mean ----
    if (s == 0) {
        __threadfence();
        unsigned tk = atomicAdd(&d_ticket, 1u);
        sLast = (tk == NBATCH - 1);
    }
    __syncthreads();
    if (sLast) {
        __threadfence();
        #pragma unroll
        for (int k = 0; k < NBATCH / NSAMP; ++k) sSum[s + k * NSAMP] = d_partial[s + k * NSAMP];
        __syncthreads();
        #pragma unroll
        for (int o = 64; o; o >>= 1) {
            if (s < o) sSum[s] += sSum[s + o];
            __syncthreads();
        }
        if (s == 0) {
            out[0] = (float)(sSum[0] / (double)NSEQ);
            d_ticket = 0;   // reset for next graph replay
        }
    }
}

// ---------------------------------------------------------------------------
extern "C" void kernel_launch(void* const* d_in, const int* in_sizes, int n_in,
                              void* d_out, int out_size) {
    const float* logp = (const float*)d_in[0];  // (128,64) f32
    const int*   ref  = (const int*)d_in[1];    // (256,128) i32
    const int*   hyp  = (const int*)d_in[2];    // (256,128,64) i32
    float* out = (float*)d_out;

    mer_loss_kernel<<<NBATCH, NSAMP>>>(hyp, ref, logp, out);
}

// round 15
// speedup vs baseline: 1.7394x; 1.7394x over previous
#include <cuda_runtime.h>
#include <cstdint>

// Shapes (fixed):
//   log_probs: (128, 64) f32 | ref: (256, 128) i32 | hyp: (256, 128, 64) i32
#define NBATCH 128
#define NSAMP  64
#define NSEQ   (NBATCH * NSAMP)   // 8192
#define RLEN   256
#define HLEN   256
#define SYMS   1024               // tokens in [0,1000); slots 1000..1023 stay zero
#define SENT   1023               // sentinel token: Peq row all-zero -> state fixed point
#define TPD    8                  // token prefetch ring depth
#define CH     32                 // carry hand-off chunk (bits per carry word)
#define NCHUNK (HLEN / CH + 1)    // 9: +1 chunk of pipeline skew

typedef unsigned long long ull;

__device__ double   d_partial[NBATCH];
__device__ unsigned d_ticket;      // zero at start; winner resets each run

// ---------------------------------------------------------------------------
// Solo Myers (R11-verified), for bsel==0 blocks (m <= 64). Plain shifts:
// both IMAD-pipe rewrites regressed; ptxas's SHF/LEA form is optimal here.
// ---------------------------------------------------------------------------
template<int NWA>
__device__ __forceinline__ int myers_solo(const ull* __restrict__ sPeq,
                                          const int* __restrict__ hyp,
                                          int n, int pm) {
    ull Pv[NWA], Mv[NWA];
    #pragma unroll
    for (int w = 0; w < NWA; ++w) { Pv[w] = ~0ull; Mv[w] = 0ull; }

    int toks[TPD];
    int tcur = hyp[n];
    #pragma unroll
    for (int k = 0; k < TPD; ++k) toks[k] = hyp[(size_t)(k + 1) * NSEQ + n];

    ull E[NWA];
    #pragma unroll
    for (int w = 0; w < NWA; ++w) E[w] = sPeq[(tcur << 2) + w];

    int score = 0, scoreF = 0, done = 0;

    #pragma unroll 1
    for (int hb = 0; hb < HLEN; hb += TPD) {
        #pragma unroll
        for (int j = 0; j < TPD; ++j) {
            const int h = hb + j;
            const int t1 = toks[j];
            ull N[NWA];
            #pragma unroll
            for (int w = 0; w < NWA; ++w) N[w] = sPeq[(t1 << 2) + w];

            const int sa = (h + 1 + TPD) & (HLEN - 1);
            toks[j] = hyp[(size_t)sa * NSEQ + n];

            ull phin = 1ull, mhin = 0ull;
            #pragma unroll
            for (int w = 0; w < NWA; ++w) {
                ull Eq = E[w];
                ull Xv = Eq | Mv[w];
                Eq |= mhin;
                ull Xh = (((Eq & Pv[w]) + Pv[w]) ^ Pv[w]) | Eq;
                ull Ph = Mv[w] | ~(Xh | Pv[w]);
                ull Mh = Pv[w] & Xh;
                ull po = Ph >> 63, mo = Mh >> 63;
                if (w == NWA - 1)
                    score += (int)((Ph >> pm) & 1ull) - (int)((Mh >> pm) & 1ull);
                Ph = (Ph << 1) | phin;
                Mh = (Mh << 1) | mhin;
                Pv[w] = Mh | ~(Xv | Ph);
                Mv[w] = Ph & Xv;
                phin = po; mhin = mo;
            }
            const int isEos = (tcur == 0);
            scoreF = (isEos & ~done) ? score : scoreF;
            done  |= isEos;
            tcur = t1;
            #pragma unroll
            for (int w = 0; w < NWA; ++w) E[w] = N[w];
        }
    }
    return done ? scoreF : score;
}

// ---------------------------------------------------------------------------
// Pair-split Myers: even lane (r=0) runs words [0,NWR); odd lane (r=1) runs
// words [NWR, 2*NWR), one CH-step chunk behind. L packs its top word's
// carry-outs (1 bit/step via funnelshift); one width-2 shuffle per chunk
// hands 2x32 carry bits to H. Inactive steps (H warm-up, L tail) use the
// sentinel token: Eq=0 + zero carries leave (Pv=~0,Mv=0) invariant, so no
// predicated state updates are needed. SW = H's local score-word index.
// ---------------------------------------------------------------------------
template<int NWR, int SW, bool TOP>
__device__ __forceinline__ int pair_run(const ull* __restrict__ sPeq,
                                        const int* __restrict__ hyp,
                                        int n, int r, int pm) {
    const int wb = r * NWR;              // word base for Peq fetch

    ull Pv[NWR], Mv[NWR];
    #pragma unroll
    for (int w = 0; w < NWR; ++w) { Pv[w] = ~0ull; Mv[w] = 0ull; }

    unsigned pw_prod = 0u, mw_prod = 0u; // L: packed carry-outs of current chunk
    int score = 0, scoreF = 0, done = 0;

    int hh = -CH * r;                    // this lane's current step index

    // token ring for steps hh..hh+TPD (sentinel outside [0,HLEN))
    auto ldtok = [&](int i) -> int {
        int t = hyp[(size_t)(i & (HLEN - 1)) * NSEQ + n];
        return ((unsigned)i < (unsigned)HLEN) ? t : SENT;
    };
    int toks[TPD];
    int tcur = ldtok(hh);
    #pragma unroll
    for (int k = 0; k < TPD; ++k) toks[k] = ldtok(hh + 1 + k);

    ull E[NWR];
    #pragma unroll
    for (int w = 0; w < NWR; ++w) E[w] = sPeq[(tcur << 2) + wb + w];

    #pragma unroll 1
    for (int c = 0; c < NCHUNK; ++c) {
        // chunk-boundary carry exchange: H gets L's previous-chunk carries.
        unsigned pw_in = __shfl_sync(0xffffffffu, pw_prod, 0, 2);
        unsigned mw_in = __shfl_sync(0xffffffffu, mw_prod, 0, 2);
        unsigned pw_use = r ? pw_in : 0xffffffffu;   // L: phin = 1 every step
        unsigned mw_use = r ? mw_in : 0u;            // L: mhin = 0 every step
        pw_prod = 0u; mw_prod = 0u;

        #pragma unroll 1
        for (int sub = 0; sub < CH / 16; ++sub) {
            #pragma unroll
            for (int j = 0; j < 16; ++j) {
                const int t1 = toks[0];
                ull N[NWR];
                #pragma unroll
                for (int w = 0; w < NWR; ++w) N[w] = sPeq[(t1 << 2) + wb + w];

                // ring rotate + refill (renamed under full unroll)
                #pragma unroll
                for (int k = 0; k < TPD - 1; ++k) toks[k] = toks[k + 1];
                toks[TPD - 1] = ldtok(hh + 1 + TPD);

                // per-step carry-in from the packed word
                ull phin = (ull)(pw_use & 1u); pw_use >>= 1;
                ull mhin = (ull)(mw_use & 1u); mw_use >>= 1;

                #pragma unroll
                for (int w = 0; w < NWR; ++w) {
                    ull Eq = E[w];
                    ull Xv = Eq | Mv[w];
                    Eq |= mhin;
                    ull Xh = (((Eq & Pv[w]) + Pv[w]) ^ Pv[w]) | Eq;
                    ull Ph = Mv[w] | ~(Xh | Pv[w]);
                    ull Mh = Pv[w] & Xh;
                    ull po = Ph >> 63, mo = Mh >> 63;
                    if (w == NWR - 1) {
                        // pack carry-out (bit j of chunk) — L's feed to H
                        pw_prod = __funnelshift_r(pw_prod, (unsigned)po, 1);
                        mw_prod = __funnelshift_r(mw_prod, (unsigned)mo, 1);
                    }
                    if (w == SW) {       // H's score word (garbage on L, discarded)
                        if (TOP) score += (int)po - (int)mo;
                        else     score += (int)((Ph >> pm) & 1ull)
                                        - (int)((Mh >> pm) & 1ull);
                    }
                    Ph = (Ph << 1) | phin;
                    Mh = (Mh << 1) | mhin;
                    Pv[w] = Mh | ~(Xv | Ph);
                    Mv[w] = Ph & Xv;
                    phin = po; mhin = mo;
                }

                // EOS capture (sentinel 1023 never triggers)
                const int isEos = (tcur == 0);
                scoreF = (isEos & ~done) ? score : scoreF;
                done  |= isEos;

                tcur = t1;
                #pragma unroll
                for (int w = 0; w < NWR; ++w) E[w] = N[w];
                ++hh;
            }
        }
    }
    return done ? scoreF : score;
}

// ---------------------------------------------------------------------------
// Fused kernel: block b = batch row b, 128 threads = 64 samples x 2 roles.
// ---------------------------------------------------------------------------
__global__ void __launch_bounds__(128, 1)
mer_loss_kernel(const int* __restrict__ hyp,
                const int* __restrict__ ref,
                const float* __restrict__ logp,
                float* __restrict__ out) {
    __shared__ ull    sPeq[SYMS * 4];   // 32 KB bitmask table
    __shared__ int    sMinEos;
    __shared__ float  sEr[NSAMP];
    __shared__ bool   sLast;
    __shared__ double sSum[NBATCH];

    const int b   = blockIdx.x;
    const int tid = threadIdx.x;        // 0..127
    const int q   = tid >> 1;           // sample 0..63
    const int r   = tid & 1;            // role: 0 = low words, 1 = high words
    const int n   = b * NSAMP + q;

    // ---- build Peq in SMEM ----
    if (tid == 0) sMinEos = RLEN;
    #pragma unroll
    for (int i = tid; i < SYMS * 4; i += 128) sPeq[i] = 0ull;
    __syncthreads();

    int rtok[2];
    #pragma unroll
    for (int k = 0; k < 2; ++k) {
        int j = tid + k * 128;
        rtok[k] = ref[(size_t)j * NBATCH + b];
        if (rtok[k] == 0) atomicMin(&sMinEos, j);
    }
    __syncthreads();
    const int m = (sMinEos < RLEN) ? (sMinEos + 1) : RLEN;  // INCLUDE_EOS
    #pragma unroll
    for (int k = 0; k < 2; ++k) {
        int j = tid + k * 128;
        if (j < m)
            atomicOr(&sPeq[(rtok[k] << 2) + (j >> 6)], 1ull << (j & 63));
    }
    __syncthreads();

    const int bsel = (m - 1) >> 6;
    const int pm   = (m - 1) & 63;

    // ---- Myers DP, dispatched on uniform word count ----
    int sdel;
    if (bsel == 0) {
        sdel = myers_solo<1>(sPeq, hyp, n, pm);            // both lanes compute
    } else if (bsel == 1) {
        sdel = pair_run<1, 0, false>(sPeq, hyp, n, r, pm); // L:w0  H:w1
    } else if (bsel == 2) {
        sdel = pair_run<2, 0, false>(sPeq, hyp, n, r, pm); // L:w0,1 H:w2,(dummy)
    } else if (pm == 63) {
        sdel = pair_run<2, 1, true >(sPeq, hyp, n, r, pm); // dominant m=256 case
    } else {
        sdel = pair_run<2, 1, false>(sPeq, hyp, n, r, pm);
    }

    if (r == 1) sEr[q] = (float)(m + sdel) / (float)m;     // H owns the score
    __syncthreads();

    // ---- per-batch softmax-weighted centered reduction (warp 0) ----
    if (tid < 32) {
        int lane = tid, base = b * NSAMP;
        float er0 = sEr[lane],         er1 = sEr[lane + 32];
        float lp0 = logp[base + lane], lp1 = logp[base + 32 + lane];

        float mx = fmaxf(lp0, lp1);
        #pragma unroll
        for (int o = 16; o; o >>= 1) mx = fmaxf(mx, __shfl_xor_sync(0xffffffffu, mx, o));

        float e0 = expf(lp0 - mx), e1 = expf(lp1 - mx);
        float se  = e0 + e1;
        float ser = er0 + er1;
        float sep = er0 * e0 + er1 * e1;
        #pragma unroll
        for (int o = 16; o; o >>= 1) {
            se  += __shfl_xor_sync(0xffffffffu, se,  o);
            ser += __shfl_xor_sync(0xffffffffu, ser, o);
            sep += __shfl_xor_sync(0xffffffffu, sep, o);
        }
        if (lane == 0)
            d_partial[b] = (double)sep / (double)se - (double)ser / 64.0;
    }
    __syncthreads();

    // ---- last-block ticket: global mean ----
    if (tid == 0) {
        __threadfence();
        unsigned tk = atomicAdd(&d_ticket, 1u);
        sLast = (tk == NBATCH - 1);
    }
    __syncthreads();
    if (sLast) {
        __threadfence();
        sSum[tid] = d_partial[tid];     // 128 threads == NBATCH entries
        __syncthreads();
        #pragma unroll
        for (int o = 64; o; o >>= 1) {
            if (tid < o) sSum[tid] += sSum[tid + o];
            __syncthreads();
        }
        if (tid == 0) {
            out[0] = (float)(sSum[0] / (double)NSEQ);
            d_ticket = 0;               // reset for next graph replay
        }
    }
}

// ---------------------------------------------------------------------------
extern "C" void kernel_launch(void* const* d_in, const int* in_sizes, int n_in,
                              void* d_out, int out_size) {
    const float* logp = (const float*)d_in[0];  // (128,64) f32
    const int*   ref  = (const int*)d_in[1];    // (256,128) i32
    const int*   hyp  = (const int*)d_in[2];    // (256,128,64) i32
    float* out = (float*)d_out;

    mer_loss_kernel<<<NBATCH, 128>>>(hyp, ref, logp, out);
}